// round 1
// baseline (speedup 1.0000x reference)
#include <cuda_runtime.h>

// Problem constants (fixed by setup_inputs)
#define B_  64
#define T_  8000
#define M_  80
#define TC  100                 // timesteps per chunk
#define NC  (T_ / TC)           // 80 chunks per batch row
#define THREADS 256
#define EPS 1e-6f

// Lookback scratch: carries (inclusive EMA state at end of each chunk) + ready flags.
// Static __device__ arrays -> no allocation. Flags reset via cudaMemsetAsync each launch.
__device__ float    g_carry[NC * B_ * M_];
__device__ unsigned g_flag [NC * B_];

__device__ __forceinline__ float fast_log2(float x) {
    float y; asm("lg2.approx.f32 %0, %1;" : "=f"(y) : "f"(x)); return y;
}
__device__ __forceinline__ float fast_exp2(float x) {
    float y; asm("ex2.approx.f32 %0, %1;" : "=f"(y) : "f"(x)); return y;
}

extern __shared__ float smem[];

__global__ __launch_bounds__(THREADS)
void pcen_lookback_kernel(const float* __restrict__ x,
                          const float* __restrict__ log_s,
                          const float* __restrict__ log_alpha,
                          const float* __restrict__ log_delta,
                          const float* __restrict__ log_r,
                          float* __restrict__ out)
{
    float*  xs = smem;                         // [TC * M_] raw input chunk
    float*  ms = smem + TC * M_;               // [TC * M_] EMA state per element
    float4* p4 = (float4*)(smem + 2 * TC * M_);// [M_] packed (-alpha, r, delta, delta^r)

    const int  bid = blockIdx.x;
    const int  b   = bid % B_;        // chunk-major ordering: all chunk-0 blocks first
    const int  c   = bid / B_;
    const int  tid = threadIdx.x;
    const long gbase = ((long)b * T_ + (long)c * TC) * M_;   // chunk is contiguous

    // ---- Phase L: coalesced vectorized load of the chunk into SMEM ----
    {
        const float4* src = (const float4*)(x + gbase);
        float4*       dst = (float4*)xs;
        for (int i = tid; i < TC * M_ / 4; i += THREADS) dst[i] = src[i];
    }

    // ---- Per-m parameter setup (threads 0..79) ----
    float s = 0.f, om = 0.f, powTc = 0.f, carry = 0.f;
    if (tid < M_) {
        const int m = tid;
        s = expf(log_s[m]);
        const float alpha = expf(log_alpha[m]);
        const float delta = expf(log_delta[m]);
        const float r     = expf(log_r[m]);
        om    = 1.0f - s;
        powTc = powf(om, (float)TC);           // decay across one whole chunk
        p4[m] = make_float4(-alpha, r, delta, powf(delta, r));
    }
    __syncthreads();

    // ---- Phase S1: chunk-local scan endpoint (initial state 0) ----
    float lend = 0.f;
    if (tid < M_) {
        const int m = tid;
        #pragma unroll 4
        for (int t = 0; t < TC; ++t)
            lend = fmaf(om, lend, s * xs[t * M_ + m]);

        // ---- Decoupled lookback: wait for predecessor chunk's inclusive state ----
        if (c > 0) {
            volatile unsigned* fl = &g_flag[(c - 1) * B_ + b];
            while (*fl == 0u) { __nanosleep(64); }
            __threadfence();
            carry = *(volatile float*)&g_carry[((c - 1) * B_ + b) * M_ + m];
        }
        const float incl = fmaf(powTc, carry, lend);   // m_{end of this chunk}
        *(volatile float*)&g_carry[(c * B_ + b) * M_ + m] = incl;
    }
    __syncthreads();
    if (tid == 0) {
        __threadfence();
        *(volatile unsigned*)&g_flag[c * B_ + b] = 1u;   // publish ASAP
    }

    // ---- Phase S2: rescan from true carry, store m_t (cheap FMA chain) ----
    if (tid < M_) {
        const int m = tid;
        float mr = carry;
        #pragma unroll 4
        for (int t = 0; t < TC; ++t) {
            mr = fmaf(om, mr, s * xs[t * M_ + m]);
            ms[t * M_ + m] = mr;
        }
    }
    __syncthreads();

    // ---- Phase O: all 256 threads, MUFU-parallel output over t x m ----
    int mi = tid % M_;                         // m index; stride 256 -> +16 mod 80
    for (int e = tid; e < TC * M_; e += THREADS) {
        const float4 P  = p4[mi];
        const float  xv = xs[e];
        const float  mv = ms[e];
        // x * (m+eps)^(-alpha)
        const float v = xv * fast_exp2(P.x * fast_log2(mv + EPS));
        // (v + delta)^r - delta^r
        const float o = fast_exp2(P.y * fast_log2(v + P.z)) - P.w;
        out[gbase + e] = o;
        mi += (THREADS % M_); if (mi >= M_) mi -= M_;
    }
}

extern "C" void kernel_launch(void* const* d_in, const int* in_sizes, int n_in,
                              void* d_out, int out_size)
{
    const float* x  = (const float*)d_in[0];
    const float* ls = (const float*)d_in[1];
    const float* la = (const float*)d_in[2];
    const float* ld = (const float*)d_in[3];
    const float* lr = (const float*)d_in[4];
    float* out = (float*)d_out;

    // Reset lookback flags (graph node, ordered before the kernel on the same stream).
    void* flag_ptr = nullptr;
    cudaGetSymbolAddress(&flag_ptr, g_flag);
    cudaMemsetAsync(flag_ptr, 0, NC * B_ * sizeof(unsigned), 0);

    const int smem_bytes = 2 * TC * M_ * (int)sizeof(float) + M_ * (int)sizeof(float4);
    cudaFuncSetAttribute(pcen_lookback_kernel,
                         cudaFuncAttributeMaxDynamicSharedMemorySize, smem_bytes);

    pcen_lookback_kernel<<<NC * B_, THREADS, smem_bytes>>>(x, ls, la, ld, lr, out);
}

// round 2
// speedup vs baseline: 1.6082x; 1.6082x over previous
#include <cuda_runtime.h>

// Problem constants (fixed by setup_inputs): B=64, T=8000, M=80
#define B_  64
#define T_  8000
#define M_  80
#define TC  100                  // timesteps per chunk
#define NC  (T_ / TC)            // 80 chunks
#define NTHREADS (NC * B_ * M_)  // 409600 = one thread per (chunk, batch, mel)
#define THREADS 256
#define EPS 1e-6f
#define SENTINEL 0xFFFFFFFFu     // float bit pattern = -NaN; lend can never be NaN

// Per-(chunk,b,m) local scan endpoints, published with release semantics.
// Reset to SENTINEL via cudaMemsetAsync each launch (graph node).
__device__ unsigned g_local[NC * B_ * M_];

__device__ __forceinline__ float fast_log2(float x) {
    float y; asm("lg2.approx.f32 %0, %1;" : "=f"(y) : "f"(x)); return y;
}
__device__ __forceinline__ float fast_exp2(float x) {
    float y; asm("ex2.approx.f32 %0, %1;" : "=f"(y) : "f"(x)); return y;
}

__global__ __launch_bounds__(THREADS)
void pcen_flat_kernel(const float* __restrict__ x,
                      const float* __restrict__ log_s,
                      const float* __restrict__ log_alpha,
                      const float* __restrict__ log_delta,
                      const float* __restrict__ log_r,
                      float* __restrict__ out)
{
    const int gtid = blockIdx.x * THREADS + threadIdx.x;   // grid covers exactly NTHREADS
    const int m  = gtid % M_;
    const int bc = gtid / M_;
    const int b  = bc % B_;
    const int c  = bc / B_;      // chunk-major: low tids = early chunks -> scheduled first

    const long gbase = ((long)b * T_ + (long)c * TC) * M_ + m;
    const float* __restrict__ xp = x + gbase;

    // ---- per-thread params (one m each) ----
    const float s     = expf(log_s[m]);
    const float om    = 1.0f - s;
    const float nalpha = -expf(log_alpha[m]);
    const float r     = expf(log_r[m]);
    const float delta = expf(log_delta[m]);
    const float delta_r = powf(delta, r);
    const float powTc   = powf(om, (float)TC);   // decay over one chunk

    // ---- S1: local scan endpoint of this chunk (initial state 0) ----
    float lend = 0.0f;
    #pragma unroll 10
    for (int t = 0; t < TC; ++t)
        lend = fmaf(om, lend, s * __ldg(xp + (long)t * M_));

    // ---- publish local endpoint immediately (no dependency on predecessors) ----
    {
        unsigned* slot = &g_local[(c * B_ + b) * M_ + m];
        asm volatile("st.release.gpu.b32 [%0], %1;"
                     :: "l"(slot), "r"(__float_as_uint(lend)) : "memory");
    }

    // ---- lookback: carry = sum of predecessors' locals with geometric weights ----
    // carry after loop equals the inclusive EMA state at end of chunk c-1:
    //   carry <- carry*om^TC + lend_j   for j = 0..c-1  (identical to serial ripple)
    float carry = 0.0f;
    for (int j = 0; j < c; ++j) {
        const unsigned* ps = &g_local[(j * B_ + b) * M_ + m];
        unsigned v;
        while (true) {
            asm volatile("ld.acquire.gpu.b32 %0, [%1];" : "=r"(v) : "l"(ps) : "memory");
            if (v != SENTINEL) break;
            __nanosleep(32);
        }
        carry = fmaf(carry, powTc, __uint_as_float(v));
    }

    // ---- S2 + output fused: rescan from true carry, compress, store ----
    float mr = carry;
    #pragma unroll 5
    for (int t = 0; t < TC; ++t) {
        const float xv = __ldg(xp + (long)t * M_);       // L2 hit (read in S1 just above)
        mr = fmaf(om, mr, s * xv);
        // v = x * (m+eps)^(-alpha)
        const float v = xv * fast_exp2(nalpha * fast_log2(mr + EPS));
        // out = (v + delta)^r - delta^r
        out[gbase + (long)t * M_] = fast_exp2(r * fast_log2(v + delta)) - delta_r;
    }
}

extern "C" void kernel_launch(void* const* d_in, const int* in_sizes, int n_in,
                              void* d_out, int out_size)
{
    const float* x  = (const float*)d_in[0];
    const float* ls = (const float*)d_in[1];
    const float* la = (const float*)d_in[2];
    const float* ld = (const float*)d_in[3];
    const float* lr = (const float*)d_in[4];
    float* out = (float*)d_out;

    // Reset publication slots to sentinel (graph node, ordered before kernel on stream 0).
    void* slots = nullptr;
    cudaGetSymbolAddress(&slots, g_local);
    cudaMemsetAsync(slots, 0xFF, NC * B_ * M_ * sizeof(unsigned), 0);

    pcen_flat_kernel<<<NTHREADS / THREADS, THREADS>>>(x, ls, la, ld, lr, out);
}

// round 3
// speedup vs baseline: 1.9436x; 1.2085x over previous
#include <cuda_runtime.h>

// Problem constants (fixed by setup_inputs): B=64, T=8000, M=80
#define B_  64
#define T_  8000
#define M_  80
#define TC  50                   // timesteps per chunk (smaller -> L2-resident between passes)
#define NC  (T_ / TC)            // 160 chunks
#define NTHREADS (NC * B_ * M_)  // 819200 threads: one per (chunk, batch, mel)
#define THREADS 256
#define EPS 1e-6f
#define SENTINEL 0xFFFFFFFFu     // -NaN bit pattern; a convex comb. of uniform[0,1) is never NaN
#define LBATCH 8                 // lookback MLP batch

// Per-(chunk,b,m) local scan endpoints. Reset to SENTINEL via cudaMemsetAsync per launch.
__device__ unsigned g_local[NC * B_ * M_];
// Precomputed per-mel parameters.
__device__ float4 g_pow[M_];   // (-alpha, r, delta, delta^r)
__device__ float4 g_ema[M_];   // (s, 1-s, (1-s)^TC, 0)

__device__ __forceinline__ float fast_log2(float x) {
    float y; asm("lg2.approx.f32 %0, %1;" : "=f"(y) : "f"(x)); return y;
}
__device__ __forceinline__ float fast_exp2(float x) {
    float y; asm("ex2.approx.f32 %0, %1;" : "=f"(y) : "f"(x)); return y;
}
__device__ __forceinline__ unsigned ld_relaxed(const unsigned* p) {
    unsigned v; asm volatile("ld.relaxed.gpu.b32 %0, [%1];" : "=r"(v) : "l"(p) : "memory");
    return v;
}
__device__ __forceinline__ void st_release(unsigned* p, unsigned v) {
    asm volatile("st.release.gpu.b32 [%0], %1;" :: "l"(p), "r"(v) : "memory");
}
__device__ __forceinline__ void st_stream(float* p, float v) {
    asm volatile("st.global.cs.f32 [%0], %1;" :: "l"(p), "f"(v) : "memory");
}

__global__ void pcen_params_kernel(const float* __restrict__ log_s,
                                   const float* __restrict__ log_alpha,
                                   const float* __restrict__ log_delta,
                                   const float* __restrict__ log_r)
{
    const int m = threadIdx.x;
    if (m < M_) {
        const float s     = expf(log_s[m]);
        const float om    = 1.0f - s;
        const float alpha = expf(log_alpha[m]);
        const float delta = expf(log_delta[m]);
        const float r     = expf(log_r[m]);
        g_pow[m] = make_float4(-alpha, r, delta, powf(delta, r));
        g_ema[m] = make_float4(s, om, powf(om, (float)TC), 0.0f);
    }
}

__global__ __launch_bounds__(THREADS)
void pcen_flat_kernel(const float* __restrict__ x, float* __restrict__ out)
{
    const int gtid = blockIdx.x * THREADS + threadIdx.x;
    const int m  = gtid % M_;
    const int bc = gtid / M_;
    const int b  = bc % B_;
    const int c  = bc / B_;      // chunk-major: low block ids = early chunks

    const long gbase = ((long)b * T_ + (long)c * TC) * M_ + m;
    const float* __restrict__ xp = x + gbase;

    const float4 E = g_ema[m];   // s, om, om^TC
    const float4 P = g_pow[m];   // -alpha, r, delta, delta^r
    const float s = E.x, om = E.y, powTc = E.z;

    // ---- S1: local scan endpoint of this chunk (initial state 0) ----
    float lend = 0.0f;
    #pragma unroll 10
    for (int t = 0; t < TC; ++t)
        lend = fmaf(om, lend, s * __ldg(xp + (long)t * M_));

    // ---- publish local endpoint immediately (no dependency on predecessors) ----
    unsigned* const slot0 = &g_local[b * M_ + m];      // stride between chunks = B_*M_
    st_release(slot0 + (long)c * (B_ * M_), __float_as_uint(lend));

    // ---- lookback: carry = serial combine of predecessors' locals, loads batched x8 ----
    float carry = 0.0f;
    int j = 0;
    for (; j + LBATCH <= c; j += LBATCH) {
        unsigned v[LBATCH];
        #pragma unroll
        for (int k = 0; k < LBATCH; ++k)               // 8 independent L2 loads (MLP)
            v[k] = ld_relaxed(slot0 + (long)(j + k) * (B_ * M_));
        #pragma unroll
        for (int k = 0; k < LBATCH; ++k)
            while (v[k] == SENTINEL) {                 // stragglers only
                __nanosleep(32);
                v[k] = ld_relaxed(slot0 + (long)(j + k) * (B_ * M_));
            }
        #pragma unroll
        for (int k = 0; k < LBATCH; ++k)
            carry = fmaf(carry, powTc, __uint_as_float(v[k]));
    }
    for (; j < c; ++j) {
        unsigned v = ld_relaxed(slot0 + (long)j * (B_ * M_));
        while (v == SENTINEL) {
            __nanosleep(32);
            v = ld_relaxed(slot0 + (long)j * (B_ * M_));
        }
        carry = fmaf(carry, powTc, __uint_as_float(v));
    }

    // ---- S2 + output fused: rescan from true carry (x re-read hits L2), compress ----
    float mr = carry;
    #pragma unroll 5
    for (int t = 0; t < TC; ++t) {
        const float xv = __ldg(xp + (long)t * M_);
        mr = fmaf(om, mr, s * xv);
        const float v = xv * fast_exp2(P.x * fast_log2(mr + EPS));   // x*(m+eps)^-alpha
        const float o = fast_exp2(P.y * fast_log2(v + P.z)) - P.w;   // (v+delta)^r - delta^r
        st_stream(out + gbase + (long)t * M_, o);                    // evict-first: keep x in L2
    }
}

extern "C" void kernel_launch(void* const* d_in, const int* in_sizes, int n_in,
                              void* d_out, int out_size)
{
    const float* x  = (const float*)d_in[0];
    const float* ls = (const float*)d_in[1];
    const float* la = (const float*)d_in[2];
    const float* ld = (const float*)d_in[3];
    const float* lr = (const float*)d_in[4];
    float* out = (float*)d_out;

    void* slots = nullptr;
    cudaGetSymbolAddress(&slots, g_local);
    cudaMemsetAsync(slots, 0xFF, NC * B_ * M_ * sizeof(unsigned), 0);

    pcen_params_kernel<<<1, 128>>>(ls, la, ld, lr);
    pcen_flat_kernel<<<NTHREADS / THREADS, THREADS>>>(x, out);
}

// round 4
// speedup vs baseline: 2.1391x; 1.1006x over previous
#include <cuda_runtime.h>

// Problem constants (fixed by setup_inputs): B=64, T=8000, M=80
#define B_  64
#define T_  8000
#define M_  80
#define TC  50                   // timesteps per chunk (L2-resident between passes)
#define NC  (T_ / TC)            // 160 chunks
#define NTHREADS (NC * B_ * M_)  // 819200 threads: one per (chunk, batch, mel)
#define THREADS 256
#define EPS 1e-6f
#define SENTINEL 0xFFFFFFFFu     // -NaN bits; convex combos of uniform[0,1) never produce this
#define LBATCH 4                 // backward-lookback prefetch batch

// Per-(chunk,b,m) slot: low 32 = local endpoint, high 32 = inclusive endpoint.
// Both sentinel-initialized via cudaMemsetAsync(0xFF) each launch.
__device__ unsigned long long g_slot[NC * B_ * M_];
// Precomputed per-mel parameters.
__device__ float4 g_pow[M_];   // (-alpha, r, delta, delta^r)
__device__ float4 g_ema[M_];   // (s, 1-s, (1-s)^TC, 0)

__device__ __forceinline__ float fast_log2(float x) {
    float y; asm("lg2.approx.f32 %0, %1;" : "=f"(y) : "f"(x)); return y;
}
__device__ __forceinline__ float fast_exp2(float x) {
    float y; asm("ex2.approx.f32 %0, %1;" : "=f"(y) : "f"(x)); return y;
}
__device__ __forceinline__ unsigned long long ld_relaxed64(const unsigned long long* p) {
    unsigned long long v;
    asm volatile("ld.relaxed.gpu.b64 %0, [%1];" : "=l"(v) : "l"(p) : "memory");
    return v;
}
__device__ __forceinline__ void st_release64(unsigned long long* p, unsigned long long v) {
    asm volatile("st.release.gpu.b64 [%0], %1;" :: "l"(p), "l"(v) : "memory");
}
__device__ __forceinline__ void st_stream(float* p, float v) {
    asm volatile("st.global.cs.f32 [%0], %1;" :: "l"(p), "f"(v) : "memory");
}

__global__ void pcen_params_kernel(const float* __restrict__ log_s,
                                   const float* __restrict__ log_alpha,
                                   const float* __restrict__ log_delta,
                                   const float* __restrict__ log_r)
{
    const int m = threadIdx.x;
    if (m < M_) {
        const float s     = expf(log_s[m]);
        const float om    = 1.0f - s;
        const float alpha = expf(log_alpha[m]);
        const float delta = expf(log_delta[m]);
        const float r     = expf(log_r[m]);
        g_pow[m] = make_float4(-alpha, r, delta, powf(delta, r));
        g_ema[m] = make_float4(s, om, powf(om, (float)TC), 0.0f);
    }
}

__global__ __launch_bounds__(THREADS)
void pcen_flat_kernel(const float* __restrict__ x, float* __restrict__ out)
{
    const int gtid = blockIdx.x * THREADS + threadIdx.x;
    const int m  = gtid % M_;
    const int bc = gtid / M_;
    const int b  = bc % B_;
    const int c  = bc / B_;      // chunk-major: low block ids = early chunks, scheduled first

    const long gbase = ((long)b * T_ + (long)c * TC) * M_ + m;
    const float* __restrict__ xp = x + gbase;

    const float4 E = g_ema[m];   // s, om, om^TC
    const float4 P = g_pow[m];   // -alpha, r, delta, delta^r
    const float s = E.x, om = E.y, powTc = E.z;

    // ---- S1: local scan endpoint of this chunk (initial state 0) ----
    float lend = 0.0f;
    #pragma unroll 10
    for (int t = 0; t < TC; ++t)
        lend = fmaf(om, lend, s * __ldg(xp + (long)t * M_));

    // ---- publish local endpoint immediately ----
    unsigned long long* const slot0 = &g_slot[b * M_ + m];  // chunk stride = B_*M_
    const unsigned lbits = __float_as_uint(lend);
    st_release64(slot0 + (long)c * (B_ * M_),
                 (unsigned long long)lbits | ((unsigned long long)SENTINEL << 32));

    // ---- two-level decoupled lookback: scan BACKWARD, stop at first inclusive ----
    float carry = 0.0f;
    {
        float acc = 0.0f, w = 1.0f;
        int j = c - 1;
        bool done = (j < 0);
        while (!done) {
            unsigned long long v[LBATCH];
            const int n = (j + 1 < LBATCH) ? (j + 1) : LBATCH;
            #pragma unroll
            for (int k = 0; k < LBATCH; ++k)          // independent prefetch (MLP)
                if (k < n) v[k] = ld_relaxed64(slot0 + (long)(j - k) * (B_ * M_));
            for (int k = 0; k < n; ++k) {
                unsigned long long pv = v[k];
                unsigned lo = (unsigned)pv, hi = (unsigned)(pv >> 32);
                while (lo == SENTINEL) {               // local not yet published: poll
                    __nanosleep(32);
                    pv = ld_relaxed64(slot0 + (long)(j - k) * (B_ * M_));
                    lo = (unsigned)pv; hi = (unsigned)(pv >> 32);
                }
                if (hi != SENTINEL) {                  // inclusive found -> terminate walk
                    carry = fmaf(w, __uint_as_float(hi), acc);
                    done = true;
                    break;
                }
                acc = fmaf(w, __uint_as_float(lo), acc);
                w  *= powTc;
            }
            if (!done) {
                j -= n;
                if (j < 0) { carry = acc; done = true; }
            }
        }
    }

    // ---- publish inclusive endpoint (accelerates all successors) ----
    const float incl = fmaf(powTc, carry, lend);
    st_release64(slot0 + (long)c * (B_ * M_),
                 (unsigned long long)lbits | ((unsigned long long)__float_as_uint(incl) << 32));

    // ---- S2 + output fused: rescan from true carry (x re-read hits L2), compress ----
    float mr = carry;
    #pragma unroll 5
    for (int t = 0; t < TC; ++t) {
        const float xv = __ldg(xp + (long)t * M_);
        mr = fmaf(om, mr, s * xv);
        const float v = xv * fast_exp2(P.x * fast_log2(mr + EPS));   // x*(m+eps)^-alpha
        const float o = fast_exp2(P.y * fast_log2(v + P.z)) - P.w;   // (v+delta)^r - delta^r
        st_stream(out + gbase + (long)t * M_, o);                    // evict-first store
    }
}

extern "C" void kernel_launch(void* const* d_in, const int* in_sizes, int n_in,
                              void* d_out, int out_size)
{
    const float* x  = (const float*)d_in[0];
    const float* ls = (const float*)d_in[1];
    const float* la = (const float*)d_in[2];
    const float* ld = (const float*)d_in[3];
    const float* lr = (const float*)d_in[4];
    float* out = (float*)d_out;

    void* slots = nullptr;
    cudaGetSymbolAddress(&slots, g_slot);
    cudaMemsetAsync(slots, 0xFF, NC * B_ * M_ * sizeof(unsigned long long), 0);

    pcen_params_kernel<<<1, 128>>>(ls, la, ld, lr);
    pcen_flat_kernel<<<NTHREADS / THREADS, THREADS>>>(x, out);
}